// round 1
// baseline (speedup 1.0000x reference)
#include <cuda_runtime.h>
#include <stdint.h>

// ---------------------------------------------------------------------------
// GPRNet: out = sum_k temp[k] * A_hat^k (MLP(x) @ W_fc) + b_fc
// MLP(x) @ W_fc is a scalar per node -> propagate scalars, not 64-dim features.
// A_hat = D^-1/2 (A + I) D^-1/2 with deg over aggregation index col (+ self).
// Factored: x_k[i] = dinv[i] * ( curw[i] + sum_{e: col=i} curw[row_e] ),
//           curw[j] = dinv[j] * x_{k-1}[j]
// ---------------------------------------------------------------------------

#define MAXN 100352
#define NBLK 256
#define EBLK 256

__device__ float g_dinv[MAXN];    // degree, then overwritten with rsqrt(deg)
__device__ float g_s[MAXN];       // MLP(x) @ W_fc per node
__device__ float g_hidden[MAXN];  // running sum_k temp[k]*x_k
__device__ float g_curw[MAXN];    // dinv[i]*x_{k-1}[i]
__device__ float g_accA[MAXN];    // ping-pong accumulators
__device__ float g_accB[MAXN];

// ---- per-node MLP + deg init -------------------------------------------------
__global__ void __launch_bounds__(NBLK) k_init(
    const float* __restrict__ x,
    const float* __restrict__ W1, const float* __restrict__ b1,
    const float* __restrict__ W2, const float* __restrict__ b2,
    const float* __restrict__ Wfc, int N)
{
    __shared__ float sW1[32], sB1[32], sB2[64], sWfc[64];
    __shared__ __align__(16) float sW2[2048];

    for (int t = threadIdx.x; t < 2048; t += blockDim.x) sW2[t] = W2[t];
    if (threadIdx.x < 32) { sW1[threadIdx.x] = W1[threadIdx.x]; sB1[threadIdx.x] = b1[threadIdx.x]; }
    if (threadIdx.x < 64) { sB2[threadIdx.x] = b2[threadIdx.x]; sWfc[threadIdx.x] = Wfc[threadIdx.x]; }
    __syncthreads();

    int i = blockIdx.x * blockDim.x + threadIdx.x;
    if (i >= N) return;

    float xv = x[i];
    float acc[64];
#pragma unroll
    for (int j = 0; j < 64; j++) acc[j] = sB2[j];

#pragma unroll
    for (int j1 = 0; j1 < 32; j1++) {
        float h = fmaxf(fmaf(xv, sW1[j1], sB1[j1]), 0.0f);
        const float4* w2r = reinterpret_cast<const float4*>(&sW2[j1 * 64]);
#pragma unroll
        for (int j = 0; j < 16; j++) {
            float4 w = w2r[j];
            acc[4*j+0] = fmaf(h, w.x, acc[4*j+0]);
            acc[4*j+1] = fmaf(h, w.y, acc[4*j+1]);
            acc[4*j+2] = fmaf(h, w.z, acc[4*j+2]);
            acc[4*j+3] = fmaf(h, w.w, acc[4*j+3]);
        }
    }
    float s = 0.0f;
#pragma unroll
    for (int j = 0; j < 64; j++) s = fmaf(fmaxf(acc[j], 0.0f), sWfc[j], s);

    g_s[i]    = s;
    g_dinv[i] = 1.0f;   // self-loop seed for degree
}

// ---- degree: deg[col] += 1 (vectorized 4 edges/thread) ----------------------
__global__ void __launch_bounds__(EBLK) k_deg_vec(const int* __restrict__ col, int E4, int rem)
{
    int t = blockIdx.x * blockDim.x + threadIdx.x;
    if (t < E4) {
        int4 c4 = reinterpret_cast<const int4*>(col)[t];
        atomicAdd(&g_dinv[c4.x], 1.0f);
        atomicAdd(&g_dinv[c4.y], 1.0f);
        atomicAdd(&g_dinv[c4.z], 1.0f);
        atomicAdd(&g_dinv[c4.w], 1.0f);
    } else if (t - E4 < rem) {
        atomicAdd(&g_dinv[col[4 * E4 + (t - E4)]], 1.0f);
    }
}

__global__ void __launch_bounds__(EBLK) k_deg_scalar(const int* __restrict__ col, int E)
{
    int e = blockIdx.x * blockDim.x + threadIdx.x;
    if (e < E) atomicAdd(&g_dinv[col[e]], 1.0f);
}

// ---- dinv finalize + first propagation step's node part ---------------------
__global__ void __launch_bounds__(NBLK) k_first(const float* __restrict__ temp, int N)
{
    int i = blockIdx.x * blockDim.x + threadIdx.x;
    if (i >= N) return;
    float d = rsqrtf(g_dinv[i]);   // deg >= 1 always (self loop)
    g_dinv[i]   = d;
    float s     = g_s[i];
    g_hidden[i] = temp[0] * s;
    float w     = d * s;
    g_curw[i]   = w;
    g_accA[i]   = w;               // self-loop contribution (pre final dinv mult)
}

// ---- per-step node kernel: finish prev step, seed next ----------------------
__global__ void __launch_bounds__(NBLK) k_node(const float* __restrict__ temp,
                                               int N, int outPar, int tempIdx)
{
    int i = blockIdx.x * blockDim.x + threadIdx.x;
    if (i >= N) return;
    const float* accIn = outPar ? g_accA : g_accB;
    float*       accOut = outPar ? g_accB : g_accA;
    float d   = g_dinv[i];
    float cur = d * accIn[i];                    // x_{k-1}[i]
    g_hidden[i] = fmaf(temp[tempIdx], cur, g_hidden[i]);
    float w   = d * cur;
    g_curw[i] = w;
    accOut[i] = w;
}

// ---- edge scatter: acc[col] += curw[row] ------------------------------------
__global__ void __launch_bounds__(EBLK) k_edge_vec(const int* __restrict__ row,
                                                   const int* __restrict__ col,
                                                   int E4, int rem, int outPar)
{
    int t = blockIdx.x * blockDim.x + threadIdx.x;
    float* acc = outPar ? g_accB : g_accA;
    if (t < E4) {
        int4 r4 = reinterpret_cast<const int4*>(row)[t];
        int4 c4 = reinterpret_cast<const int4*>(col)[t];
        atomicAdd(acc + c4.x, __ldg(&g_curw[r4.x]));
        atomicAdd(acc + c4.y, __ldg(&g_curw[r4.y]));
        atomicAdd(acc + c4.z, __ldg(&g_curw[r4.z]));
        atomicAdd(acc + c4.w, __ldg(&g_curw[r4.w]));
    } else if (t - E4 < rem) {
        int e = 4 * E4 + (t - E4);
        atomicAdd(acc + col[e], __ldg(&g_curw[row[e]]));
    }
}

__global__ void __launch_bounds__(EBLK) k_edge_scalar(const int* __restrict__ row,
                                                      const int* __restrict__ col,
                                                      int E, int outPar)
{
    int e = blockIdx.x * blockDim.x + threadIdx.x;
    float* acc = outPar ? g_accB : g_accA;
    if (e < E) atomicAdd(acc + col[e], __ldg(&g_curw[row[e]]));
}

// ---- final: add last hop, bias, write out -----------------------------------
__global__ void __launch_bounds__(NBLK) k_final(const float* __restrict__ temp,
                                                const float* __restrict__ bfc,
                                                float* __restrict__ out,
                                                int N, int lastPar, int K)
{
    int i = blockIdx.x * blockDim.x + threadIdx.x;
    if (i >= N) return;
    const float* acc = lastPar ? g_accB : g_accA;
    float cur = g_dinv[i] * acc[i];              // x_K[i]
    out[i] = g_hidden[i] + temp[K] * cur + bfc[0];
}

// ---------------------------------------------------------------------------
extern "C" void kernel_launch(void* const* d_in, const int* in_sizes, int n_in,
                              void* d_out, int out_size)
{
    const float* x    = (const float*)d_in[0];
    const int*   ei   = (const int*)  d_in[1];
    const float* W1   = (const float*)d_in[2];
    const float* b1   = (const float*)d_in[3];
    const float* W2   = (const float*)d_in[4];
    const float* b2   = (const float*)d_in[5];
    const float* temp = (const float*)d_in[6];
    const float* Wfc  = (const float*)d_in[7];
    const float* bfc  = (const float*)d_in[8];
    float*       out  = (float*)d_out;

    int N = in_sizes[0];            // x is [N,1]
    int E = in_sizes[1] / 2;        // edge_index is [2,E]
    int K = in_sizes[6] - 1;        // temp has K+1 coefficients

    const int* row = ei;
    const int* col = ei + E;

    int nb = (N + NBLK - 1) / NBLK;

    bool vec_ok = (E % 4 == 0);     // guarantees 16B alignment of both row & col
    int  E4 = E >> 2, rem = E & 3;
    int  eb_vec = (E4 + rem + EBLK - 1) / EBLK;
    int  eb_sca = (E + EBLK - 1) / EBLK;

    k_init<<<nb, NBLK>>>(x, W1, b1, W2, b2, Wfc, N);

    if (vec_ok) k_deg_vec<<<eb_vec, EBLK>>>(col, E4, rem);
    else        k_deg_scalar<<<eb_sca, EBLK>>>(col, E);

    k_first<<<nb, NBLK>>>(temp, N);

    // step 1 edge scatter (acc = A, parity 0)
    if (vec_ok) k_edge_vec<<<eb_vec, EBLK>>>(row, col, E4, rem, 0);
    else        k_edge_scalar<<<eb_sca, EBLK>>>(row, col, E, 0);

    int lastPar = 0;
    for (int k = 2; k <= K; k++) {
        int outPar = (k & 1) ? 0 : 1;
        k_node<<<nb, NBLK>>>(temp, N, outPar, k - 1);
        if (vec_ok) k_edge_vec<<<eb_vec, EBLK>>>(row, col, E4, rem, outPar);
        else        k_edge_scalar<<<eb_sca, EBLK>>>(row, col, E, outPar);
        lastPar = outPar;
    }

    k_final<<<nb, NBLK>>>(temp, bfc, out, N, lastPar, K);
}

// round 3
// speedup vs baseline: 1.0364x; 1.0364x over previous
#include <cuda_runtime.h>
#include <stdint.h>

// ---------------------------------------------------------------------------
// GPRNet scalar-propagation + per-call counting sort of edges by destination.
// out = sum_k temp[k] * A_hat^k (MLP(x) @ W_fc) + b_fc
// A_hat = D^-1/2 (A+I) D^-1/2, deg over col (+self).
// Counting sort by col -> each hop is an atomic-free segment-sum:
//   cur_new[i] = dinv[i] * ( curw[i] + sum_{e in seg(i)} curw[srow[e]] )
//   curw[j] = dinv[j] * cur[j]
// ---------------------------------------------------------------------------

#define MAXN   100352
#define MAXE   3276800
#define NBLK   256
#define EBLK   256
#define SCANB  1024
#define MAXSB  128           // max scan blocks (ceil(MAXN/1024)=98)

__device__ int   g_deg[MAXN];        // histogram of col (in-degree, no self)
__device__ int   g_off[MAXN + 1];    // exclusive prefix (CSC offsets)
__device__ int   g_cursor[MAXN];     // scatter cursors
__device__ int   g_blk[MAXSB];       // scan block sums
__device__ int   g_srow[MAXE];       // edges' source, sorted by col
__device__ float g_dinv[MAXN];
__device__ float g_s[MAXN];          // MLP(x) @ W_fc
__device__ float g_hidden[MAXN];     // running sum_k temp[k]*x_k
__device__ float g_curwA[MAXN];      // ping-pong: dinv[i]*x_k[i]
__device__ float g_curwB[MAXN];

// ---- per-node MLP (+ zero histogram) ---------------------------------------
__global__ void __launch_bounds__(NBLK) k_mlp(
    const float* __restrict__ x,
    const float* __restrict__ W1, const float* __restrict__ b1,
    const float* __restrict__ W2, const float* __restrict__ b2,
    const float* __restrict__ Wfc, int N)
{
    __shared__ float sW1[32], sB1[32], sB2[64], sWfc[64];
    __shared__ __align__(16) float sW2[2048];

    for (int t = threadIdx.x; t < 2048; t += blockDim.x) sW2[t] = W2[t];
    if (threadIdx.x < 32) { sW1[threadIdx.x] = W1[threadIdx.x]; sB1[threadIdx.x] = b1[threadIdx.x]; }
    if (threadIdx.x < 64) { sB2[threadIdx.x] = b2[threadIdx.x]; sWfc[threadIdx.x] = Wfc[threadIdx.x]; }
    __syncthreads();

    int i = blockIdx.x * blockDim.x + threadIdx.x;
    if (i >= N) return;

    float xv = x[i];
    float acc[64];
#pragma unroll
    for (int j = 0; j < 64; j++) acc[j] = sB2[j];
#pragma unroll
    for (int j1 = 0; j1 < 32; j1++) {
        float h = fmaxf(fmaf(xv, sW1[j1], sB1[j1]), 0.0f);
        const float4* w2r = reinterpret_cast<const float4*>(&sW2[j1 * 64]);
#pragma unroll
        for (int j = 0; j < 16; j++) {
            float4 w = w2r[j];
            acc[4*j+0] = fmaf(h, w.x, acc[4*j+0]);
            acc[4*j+1] = fmaf(h, w.y, acc[4*j+1]);
            acc[4*j+2] = fmaf(h, w.z, acc[4*j+2]);
            acc[4*j+3] = fmaf(h, w.w, acc[4*j+3]);
        }
    }
    float s = 0.0f;
#pragma unroll
    for (int j = 0; j < 64; j++) s = fmaf(fmaxf(acc[j], 0.0f), sWfc[j], s);

    g_s[i]   = s;
    g_deg[i] = 0;
}

// ---- histogram of col --------------------------------------------------------
__global__ void __launch_bounds__(EBLK) k_hist_vec(const int* __restrict__ col, int E4, int rem)
{
    int t = blockIdx.x * blockDim.x + threadIdx.x;
    if (t < E4) {
        int4 c4 = reinterpret_cast<const int4*>(col)[t];
        atomicAdd(&g_deg[c4.x], 1);
        atomicAdd(&g_deg[c4.y], 1);
        atomicAdd(&g_deg[c4.z], 1);
        atomicAdd(&g_deg[c4.w], 1);
    } else if (t - E4 < rem) {
        atomicAdd(&g_deg[col[4 * E4 + (t - E4)]], 1);
    }
}
__global__ void __launch_bounds__(EBLK) k_hist_sca(const int* __restrict__ col, int E)
{
    int e = blockIdx.x * blockDim.x + threadIdx.x;
    if (e < E) atomicAdd(&g_deg[col[e]], 1);
}

// ---- 3-kernel exclusive scan of g_deg -> g_off ------------------------------
__global__ void __launch_bounds__(SCANB) k_scan1(int N)
{
    __shared__ int sh[SCANB];
    int i = blockIdx.x * SCANB + threadIdx.x;
    int v = (i < N) ? g_deg[i] : 0;
    sh[threadIdx.x] = v;
    __syncthreads();
#pragma unroll
    for (int d = 1; d < SCANB; d <<= 1) {
        int t = (threadIdx.x >= d) ? sh[threadIdx.x - d] : 0;
        __syncthreads();
        sh[threadIdx.x] += t;
        __syncthreads();
    }
    int incl = sh[threadIdx.x];
    if (i < N) g_off[i] = incl - v;        // exclusive within block
    if (threadIdx.x == SCANB - 1) g_blk[blockIdx.x] = incl;
}

__global__ void __launch_bounds__(MAXSB) k_scan2(int nb)
{
    __shared__ int sh[MAXSB];
    int v = (threadIdx.x < nb) ? g_blk[threadIdx.x] : 0;
    sh[threadIdx.x] = v;
    __syncthreads();
#pragma unroll
    for (int d = 1; d < MAXSB; d <<= 1) {
        int t = (threadIdx.x >= d) ? sh[threadIdx.x - d] : 0;
        __syncthreads();
        sh[threadIdx.x] += t;
        __syncthreads();
    }
    if (threadIdx.x < nb) g_blk[threadIdx.x] = sh[threadIdx.x] - v;  // exclusive
}

// ---- scan fixup + dinv finalize + hop-0 seed (fused) -------------------------
__global__ void __launch_bounds__(SCANB) k_scan3(const float* __restrict__ temp, int N, int E)
{
    int i = blockIdx.x * SCANB + threadIdx.x;
    if (i >= N) return;
    int val = g_off[i] + g_blk[i >> 10];
    g_off[i]    = val;
    g_cursor[i] = val;
    if (i == 0) g_off[N] = E;

    float d = rsqrtf((float)(g_deg[i] + 1));   // +1 self-loop
    g_dinv[i]   = d;
    float s     = g_s[i];
    g_hidden[i] = temp[0] * s;
    g_curwA[i]  = d * s;
}

// ---- scatter edges into CSC order -------------------------------------------
__global__ void __launch_bounds__(EBLK) k_scatter_vec(const int* __restrict__ row,
                                                      const int* __restrict__ col,
                                                      int E4, int rem)
{
    int t = blockIdx.x * blockDim.x + threadIdx.x;
    if (t < E4) {
        int4 r4 = reinterpret_cast<const int4*>(row)[t];
        int4 c4 = reinterpret_cast<const int4*>(col)[t];
        g_srow[atomicAdd(&g_cursor[c4.x], 1)] = r4.x;
        g_srow[atomicAdd(&g_cursor[c4.y], 1)] = r4.y;
        g_srow[atomicAdd(&g_cursor[c4.z], 1)] = r4.z;
        g_srow[atomicAdd(&g_cursor[c4.w], 1)] = r4.w;
    } else if (t - E4 < rem) {
        int e = 4 * E4 + (t - E4);
        g_srow[atomicAdd(&g_cursor[col[e]], 1)] = row[e];
    }
}
__global__ void __launch_bounds__(EBLK) k_scatter_sca(const int* __restrict__ row,
                                                      const int* __restrict__ col, int E)
{
    int e = blockIdx.x * blockDim.x + threadIdx.x;
    if (e < E) g_srow[atomicAdd(&g_cursor[col[e]], 1)] = row[e];
}

// ---- one propagation hop: warp per node, atomic-free segment sum ------------
__global__ void __launch_bounds__(NBLK) k_hop(const float* __restrict__ temp,
                                              const float* __restrict__ bfc,
                                              float* __restrict__ out,
                                              int N, int parity, int tempIdx, int isLast)
{
    int warpInBlk = threadIdx.x >> 5;
    int lane      = threadIdx.x & 31;
    int node      = blockIdx.x * (NBLK / 32) + warpInBlk;
    if (node >= N) return;

    const float* curwIn = parity ? g_curwB : g_curwA;
    float*       curwOut = parity ? g_curwA : g_curwB;

    int start = g_off[node];
    int end   = g_off[node + 1];

    float sum = 0.0f;
    for (int e = start + lane; e < end; e += 32)
        sum += __ldg(&curwIn[__ldg(&g_srow[e])]);

#pragma unroll
    for (int d = 16; d > 0; d >>= 1)
        sum += __shfl_xor_sync(0xFFFFFFFFu, sum, d);

    if (lane == 0) {
        float dv  = g_dinv[node];
        float cur = dv * (curwIn[node] + sum);
        if (isLast) {
            out[node] = fmaf(temp[tempIdx], cur, g_hidden[node]) + bfc[0];
        } else {
            g_hidden[node] = fmaf(temp[tempIdx], cur, g_hidden[node]);
            curwOut[node]  = dv * cur;
        }
    }
}

// ---------------------------------------------------------------------------
extern "C" void kernel_launch(void* const* d_in, const int* in_sizes, int n_in,
                              void* d_out, int out_size)
{
    const float* x    = (const float*)d_in[0];
    const int*   ei   = (const int*)  d_in[1];
    const float* W1   = (const float*)d_in[2];
    const float* b1   = (const float*)d_in[3];
    const float* W2   = (const float*)d_in[4];
    const float* b2   = (const float*)d_in[5];
    const float* temp = (const float*)d_in[6];
    const float* Wfc  = (const float*)d_in[7];
    const float* bfc  = (const float*)d_in[8];
    float*       out  = (float*)d_out;

    int N = in_sizes[0];
    int E = in_sizes[1] / 2;
    int K = in_sizes[6] - 1;

    const int* row = ei;
    const int* col = ei + E;

    int nb = (N + NBLK - 1) / NBLK;
    int nscan = (N + SCANB - 1) / SCANB;

    bool vec_ok = (E % 4 == 0);
    int  E4 = E >> 2, rem = E & 3;
    int  eb_vec = (E4 + rem + EBLK - 1) / EBLK;
    int  eb_sca = (E + EBLK - 1) / EBLK;

    // MLP + zero histogram
    k_mlp<<<nb, NBLK>>>(x, W1, b1, W2, b2, Wfc, N);

    // counting sort by col (scan3 also finalizes dinv + seeds hop 0)
    if (vec_ok) k_hist_vec<<<eb_vec, EBLK>>>(col, E4, rem);
    else        k_hist_sca<<<eb_sca, EBLK>>>(col, E);
    k_scan1<<<nscan, SCANB>>>(N);
    k_scan2<<<1, MAXSB>>>(nscan);
    k_scan3<<<nscan, SCANB>>>(temp, N, E);
    if (vec_ok) k_scatter_vec<<<eb_vec, EBLK>>>(row, col, E4, rem);
    else        k_scatter_sca<<<eb_sca, EBLK>>>(row, col, E);

    // propagate
    int hop_blocks = (N + (NBLK / 32) - 1) / (NBLK / 32);
    for (int k = 1; k <= K; k++) {
        int parity = 1 - (k & 1);          // k odd: read A, write B
        k_hop<<<hop_blocks, NBLK>>>(temp, bfc, out, N, parity, k, (k == K) ? 1 : 0);
    }
}